// round 3
// baseline (speedup 1.0000x reference)
#include <cuda_runtime.h>
#include <mma.h>
#include <math.h>

using namespace nvcuda;

#define DIMD   512
#define DEPTH  4
#define NHEAD  8
#define DHEAD  64
#define INNERD 512
#define MLPD   2048
#define SEQ    2048
#define BATCH  4
#define ROWS   (BATCH * SEQ)   // 8192
#define SCALEF 0.125f          // 64^-0.5

// ---------------- scratch (device globals: allocation-free) ----------------
__device__ float g_X[ROWS * DIMD];        // residual stream
__device__ float g_H[ROWS * DIMD];        // layernorm output
__device__ float g_QKV[ROWS * 3 * INNERD];
__device__ float g_ATT[ROWS * DIMD];
__device__ float g_FF[ROWS * MLPD];

// ---------------- LayerNorm: one block (128 threads) per row ----------------
__global__ void __launch_bounds__(128) ln_kernel(const float* __restrict__ in,
                                                 const float* __restrict__ g,
                                                 const float* __restrict__ b,
                                                 float* __restrict__ out) {
    int row = blockIdx.x;
    const float4* ip = (const float4*)(in + (size_t)row * DIMD);
    float4 v = ip[threadIdx.x];               // 128 threads * 4 = 512
    float s  = v.x + v.y + v.z + v.w;
    float s2 = v.x * v.x + v.y * v.y + v.z * v.z + v.w * v.w;
    __shared__ float red[8];
    #pragma unroll
    for (int o = 16; o; o >>= 1) {
        s  += __shfl_xor_sync(0xffffffffu, s,  o);
        s2 += __shfl_xor_sync(0xffffffffu, s2, o);
    }
    int wid = threadIdx.x >> 5, lane = threadIdx.x & 31;
    if (lane == 0) { red[wid] = s; red[4 + wid] = s2; }
    __syncthreads();
    s  = red[0] + red[1] + red[2] + red[3];
    s2 = red[4] + red[5] + red[6] + red[7];
    float mu  = s * (1.0f / DIMD);
    float var = s2 * (1.0f / DIMD) - mu * mu;
    float r = rsqrtf(var + 1e-5f);
    int c = threadIdx.x * 4;
    float4 gv = *(const float4*)(g + c);
    float4 bv = *(const float4*)(b + c);
    float4 o;
    o.x = (v.x - mu) * r * gv.x + bv.x;
    o.y = (v.y - mu) * r * gv.y + bv.y;
    o.z = (v.z - mu) * r * gv.z + bv.z;
    o.w = (v.w - mu) * r * gv.w + bv.w;
    ((float4*)(out + (size_t)row * DIMD))[threadIdx.x] = o;
}

// ---------------- tf32 GEMM: C = act(A@B + bias) + resid -------------------
// Block tile 128x64, BK=16, 8 warps of 32x32 (2x2 m16n16k8 frags).
// Register-prefetch + double-buffered smem: one barrier per K-chunk.
// All shapes here are exact multiples of the tiles -> no bounds checks.
#define GBM 128
#define GBN 64
#define GBK 16
#define GLDB (GBN + 8)   // 72
#define GLDC (GBN + 8)

__device__ __forceinline__ float gelu_exact(float x) {
    return 0.5f * x * (1.0f + erff(x * 0.70710678118654752f));
}

template <int ACT>
__global__ void __launch_bounds__(256) gemm_kernel(
    const float* __restrict__ A, const float* __restrict__ B,
    const float* __restrict__ bias, const float* __restrict__ resid,
    float* __restrict__ C, int M, int N, int K) {
    __shared__ __align__(16) union {
        struct { float As[GBM][GBK]; float Bs[GBK][GLDB]; } ab[2];
        float Cs[GBM][GLDC];
    } sm;

    int tid = threadIdx.x;
    int wid = tid >> 5;
    int wm  = wid & 3;   // 0..3  (M)
    int wn  = wid >> 2;  // 0..1  (N)
    int bm = blockIdx.y * GBM;
    int bn = blockIdx.x * GBN;

    // per-thread staging coordinates
    int ar0 = tid >> 2;            // A row for slot 0 (0..63)
    int ac  = (tid & 3) * 4;       // A col (0..12)
    int br  = tid >> 4;            // B row (0..15)
    int bc  = (tid & 15) * 4;      // B col (0..60)
    const float* Aptr = A + (size_t)(bm + ar0) * K + ac;          // +64 rows for slot 1
    const float* Bptr = B + (size_t)br * N + bn + bc;

    wmma::fragment<wmma::accumulator, 16, 16, 8, float> acc[2][2];
    #pragma unroll
    for (int im = 0; im < 2; im++)
        #pragma unroll
        for (int jn = 0; jn < 2; jn++) wmma::fill_fragment(acc[im][jn], 0.0f);

    // prefetch first K-chunk into registers
    float4 ra0 = *(const float4*)(Aptr);
    float4 ra1 = *(const float4*)(Aptr + (size_t)64 * K);
    float4 rb  = *(const float4*)(Bptr);

    int buf = 0;
    for (int k0 = 0; k0 < K; k0 += GBK) {
        // store current chunk (with tf32 rounding) into stage `buf`
        {
            float* as0 = &sm.ab[buf].As[ar0][ac];
            as0[0] = wmma::__float_to_tf32(ra0.x);
            as0[1] = wmma::__float_to_tf32(ra0.y);
            as0[2] = wmma::__float_to_tf32(ra0.z);
            as0[3] = wmma::__float_to_tf32(ra0.w);
            float* as1 = &sm.ab[buf].As[64 + ar0][ac];
            as1[0] = wmma::__float_to_tf32(ra1.x);
            as1[1] = wmma::__float_to_tf32(ra1.y);
            as1[2] = wmma::__float_to_tf32(ra1.z);
            as1[3] = wmma::__float_to_tf32(ra1.w);
            float* bs = &sm.ab[buf].Bs[br][bc];
            bs[0] = wmma::__float_to_tf32(rb.x);
            bs[1] = wmma::__float_to_tf32(rb.y);
            bs[2] = wmma::__float_to_tf32(rb.z);
            bs[3] = wmma::__float_to_tf32(rb.w);
        }
        __syncthreads();

        // issue next chunk's loads early (latency hides behind the MMAs)
        if (k0 + GBK < K) {
            const float* ap = Aptr + (k0 + GBK);
            ra0 = *(const float4*)(ap);
            ra1 = *(const float4*)(ap + (size_t)64 * K);
            rb  = *(const float4*)(Bptr + (size_t)(k0 + GBK) * N);
        }

        #pragma unroll
        for (int kk = 0; kk < 2; kk++) {
            wmma::fragment<wmma::matrix_a, 16, 16, 8, wmma::precision::tf32, wmma::row_major> af[2];
            wmma::fragment<wmma::matrix_b, 16, 16, 8, wmma::precision::tf32, wmma::row_major> bf[2];
            #pragma unroll
            for (int im = 0; im < 2; im++)
                wmma::load_matrix_sync(af[im], &sm.ab[buf].As[wm * 32 + im * 16][kk * 8], GBK);
            #pragma unroll
            for (int jn = 0; jn < 2; jn++)
                wmma::load_matrix_sync(bf[jn], &sm.ab[buf].Bs[kk * 8][wn * 32 + jn * 16], GLDB);
            #pragma unroll
            for (int im = 0; im < 2; im++)
                #pragma unroll
                for (int jn = 0; jn < 2; jn++)
                    wmma::mma_sync(acc[im][jn], af[im], bf[jn], acc[im][jn]);
        }
        buf ^= 1;
        // no second barrier: the next iteration's barrier (after its stores to
        // the *other* stage) already orders reads of this stage before the
        // iteration-after-next overwrites it.
    }
    __syncthreads();   // all MMAs done before Cs aliases the stage memory

    // epilogue through shared
    #pragma unroll
    for (int im = 0; im < 2; im++)
        #pragma unroll
        for (int jn = 0; jn < 2; jn++)
            wmma::store_matrix_sync(&sm.Cs[wm * 32 + im * 16][wn * 32 + jn * 16],
                                    acc[im][jn], GLDC, wmma::mem_row_major);
    __syncthreads();

    #pragma unroll
    for (int i = 0; i < 8; i++) {
        int f = tid + i * 256;   // 0..2047
        int r = f >> 4;
        int c = (f & 15) * 4;
        float4 v = *(float4*)&sm.Cs[r][c];
        if (bias) {
            float4 bv = *(const float4*)(bias + bn + c);
            v.x += bv.x; v.y += bv.y; v.z += bv.z; v.w += bv.w;
        }
        if (ACT == 1) {
            v.x = gelu_exact(v.x); v.y = gelu_exact(v.y);
            v.z = gelu_exact(v.z); v.w = gelu_exact(v.w);
        }
        size_t off = (size_t)(bm + r) * N + bn + c;
        if (resid) {
            float4 rv = *(const float4*)(resid + off);
            v.x += rv.x; v.y += rv.y; v.z += rv.z; v.w += rv.w;
        }
        *(float4*)(C + off) = v;
    }
}

// ---------------- flash attention: block = (b, h, 64-query tile) ------------
// Register-prefetch of the next K/V tile hides gmem latency behind the
// S = QK^T / softmax / PV compute of the current tile.
#define AT  64
#define ALD 72
#define ASMEM ((5 * AT * ALD + 2 * AT) * (int)sizeof(float))

__global__ void __launch_bounds__(256) attn_kernel(const float* __restrict__ qkv,
                                                   float* __restrict__ outp) {
    extern __shared__ __align__(16) float sh[];
    float* Qs = sh;
    float* Ks = Qs + AT * ALD;
    float* Vs = Ks + AT * ALD;
    float* Ss = Vs + AT * ALD;
    float* Os = Ss + AT * ALD;
    float* m_s = Os + AT * ALD;   // [64]
    float* l_s = m_s + AT;        // [64]

    int tid = threadIdx.x;
    int wid = tid >> 5;
    int b = blockIdx.z, h = blockIdx.y;
    int q0 = blockIdx.x * AT;
    size_t baserow = (size_t)b * SEQ;

    // per-thread staging coordinates (4 quads per thread)
    int sr[4], sc[4];
    #pragma unroll
    for (int i = 0; i < 4; i++) {
        int f = tid + i * 256;        // 0..1023
        sr[i] = f >> 4;               // 0..63
        sc[i] = (f & 15) * 4;         // 0..60
    }

    // load scaled Q tile as tf32, zero O
    #pragma unroll
    for (int i = 0; i < 4; i++) {
        int r = sr[i], c = sc[i];
        float4 v = *(const float4*)(qkv + (baserow + q0 + r) * (3 * INNERD) + h * DHEAD + c);
        Qs[r * ALD + c + 0] = wmma::__float_to_tf32(v.x * SCALEF);
        Qs[r * ALD + c + 1] = wmma::__float_to_tf32(v.y * SCALEF);
        Qs[r * ALD + c + 2] = wmma::__float_to_tf32(v.z * SCALEF);
        Qs[r * ALD + c + 3] = wmma::__float_to_tf32(v.w * SCALEF);
        float4 z = make_float4(0.f, 0.f, 0.f, 0.f);
        *(float4*)&Os[r * ALD + c] = z;
    }
    if (tid < AT) { m_s[tid] = -INFINITY; l_s[tid] = 0.0f; }

    // prefetch K/V tile for j0 = 0 into registers
    float4 pk[4], pv[4];
    #pragma unroll
    for (int i = 0; i < 4; i++) {
        const float* rowp = qkv + (baserow + sr[i]) * (3 * INNERD) + h * DHEAD + sc[i];
        pk[i] = *(const float4*)(rowp + INNERD);
        pv[i] = *(const float4*)(rowp + 2 * INNERD);
    }
    __syncthreads();

    for (int j0 = 0; j0 < SEQ; j0 += AT) {
        // stage prefetched K, V tiles (tf32)
        #pragma unroll
        for (int i = 0; i < 4; i++) {
            int r = sr[i], c = sc[i];
            Ks[r * ALD + c + 0] = wmma::__float_to_tf32(pk[i].x);
            Ks[r * ALD + c + 1] = wmma::__float_to_tf32(pk[i].y);
            Ks[r * ALD + c + 2] = wmma::__float_to_tf32(pk[i].z);
            Ks[r * ALD + c + 3] = wmma::__float_to_tf32(pk[i].w);
            Vs[r * ALD + c + 0] = wmma::__float_to_tf32(pv[i].x);
            Vs[r * ALD + c + 1] = wmma::__float_to_tf32(pv[i].y);
            Vs[r * ALD + c + 2] = wmma::__float_to_tf32(pv[i].z);
            Vs[r * ALD + c + 3] = wmma::__float_to_tf32(pv[i].w);
        }
        __syncthreads();

        // issue next tile's loads early: latency hides behind S/softmax/PV
        if (j0 + AT < SEQ) {
            #pragma unroll
            for (int i = 0; i < 4; i++) {
                const float* rowp = qkv + (baserow + j0 + AT + sr[i]) * (3 * INNERD)
                                    + h * DHEAD + sc[i];
                pk[i] = *(const float4*)(rowp + INNERD);
                pv[i] = *(const float4*)(rowp + 2 * INNERD);
            }
        }

        // S = Q @ K^T  (16 frags of 16x16, 2 per warp)
        #pragma unroll
        for (int t = 0; t < 2; t++) {
            int f = wid * 2 + t;
            int fm = f >> 2, fn = f & 3;
            wmma::fragment<wmma::accumulator, 16, 16, 8, float> sacc;
            wmma::fill_fragment(sacc, 0.0f);
            #pragma unroll
            for (int k = 0; k < DHEAD; k += 8) {
                wmma::fragment<wmma::matrix_a, 16, 16, 8, wmma::precision::tf32, wmma::row_major> af;
                wmma::fragment<wmma::matrix_b, 16, 16, 8, wmma::precision::tf32, wmma::col_major> bf;
                wmma::load_matrix_sync(af, &Qs[fm * 16 * ALD + k], ALD);
                wmma::load_matrix_sync(bf, &Ks[fn * 16 * ALD + k], ALD);
                wmma::mma_sync(sacc, af, bf, sacc);
            }
            wmma::store_matrix_sync(&Ss[fm * 16 * ALD + fn * 16], sacc, ALD, wmma::mem_row_major);
        }
        __syncthreads();

        // online softmax (4 threads per row, 16 cols each)
        {
            int row = tid >> 2;
            int qq  = tid & 3;
            float* srow = Ss + row * ALD + qq * 16;
            float tmax = -INFINITY;
            #pragma unroll
            for (int c = 0; c < 16; c++) tmax = fmaxf(tmax, srow[c]);
            tmax = fmaxf(tmax, __shfl_xor_sync(0xffffffffu, tmax, 1));
            tmax = fmaxf(tmax, __shfl_xor_sync(0xffffffffu, tmax, 2));
            float mold = m_s[row];
            float mnew = fmaxf(mold, tmax);
            float alpha = __expf(mold - mnew);
            float sum = 0.0f;
            #pragma unroll
            for (int c = 0; c < 16; c++) {
                float p = __expf(srow[c] - mnew);
                sum += p;
                srow[c] = wmma::__float_to_tf32(p);
            }
            sum += __shfl_xor_sync(0xffffffffu, sum, 1);
            sum += __shfl_xor_sync(0xffffffffu, sum, 2);
            float* orow = Os + row * ALD + qq * 16;
            #pragma unroll
            for (int c = 0; c < 16; c++) orow[c] *= alpha;
            if (qq == 0) { m_s[row] = mnew; l_s[row] = l_s[row] * alpha + sum; }
        }
        __syncthreads();

        // O += P @ V
        #pragma unroll
        for (int t = 0; t < 2; t++) {
            int f = wid * 2 + t;
            int fm = f >> 2, fn = f & 3;
            wmma::fragment<wmma::accumulator, 16, 16, 8, float> oacc;
            wmma::load_matrix_sync(oacc, &Os[fm * 16 * ALD + fn * 16], ALD, wmma::mem_row_major);
            #pragma unroll
            for (int k = 0; k < AT; k += 8) {
                wmma::fragment<wmma::matrix_a, 16, 16, 8, wmma::precision::tf32, wmma::row_major> af;
                wmma::fragment<wmma::matrix_b, 16, 16, 8, wmma::precision::tf32, wmma::row_major> bf;
                wmma::load_matrix_sync(af, &Ss[fm * 16 * ALD + k], ALD);
                wmma::load_matrix_sync(bf, &Vs[k * ALD + fn * 16], ALD);
                wmma::mma_sync(oacc, af, bf, oacc);
            }
            wmma::store_matrix_sync(&Os[fm * 16 * ALD + fn * 16], oacc, ALD, wmma::mem_row_major);
        }
        __syncthreads();   // orders PV reads of Ks/Vs before next restage
    }

    // write O / l back to [b, n, h*64 + d]
    {
        int row = tid >> 2;
        int qq  = tid & 3;
        float inv = 1.0f / l_s[row];
        float* orow = Os + row * ALD + qq * 16;
        float* dst = outp + (baserow + q0 + row) * DIMD + h * DHEAD + qq * 16;
        #pragma unroll
        for (int c = 0; c < 16; c += 4) {
            float4 v = *(float4*)&orow[c];
            v.x *= inv; v.y *= inv; v.z *= inv; v.w *= inv;
            *(float4*)&dst[c] = v;
        }
    }
}

// ---------------- launch ----------------
extern "C" void kernel_launch(void* const* d_in, const int* in_sizes, int n_in,
                              void* d_out, int out_size) {
    (void)in_sizes; (void)n_in; (void)out_size;
    const float* x    = (const float*)d_in[0];
    const float* Wqkv = (const float*)d_in[1];
    const float* Wo   = (const float*)d_in[2];
    const float* bo   = (const float*)d_in[3];
    const float* ln1g = (const float*)d_in[4];
    const float* ln1b = (const float*)d_in[5];
    const float* W1   = (const float*)d_in[6];
    const float* b1   = (const float*)d_in[7];
    const float* W2   = (const float*)d_in[8];
    const float* b2   = (const float*)d_in[9];
    const float* ln2g = (const float*)d_in[10];
    const float* ln2b = (const float*)d_in[11];
    const float* lnfg = (const float*)d_in[12];
    const float* lnfb = (const float*)d_in[13];
    float* out = (float*)d_out;

    float *X, *H, *QKV, *ATT, *FF;
    cudaGetSymbolAddress((void**)&X,   g_X);
    cudaGetSymbolAddress((void**)&H,   g_H);
    cudaGetSymbolAddress((void**)&QKV, g_QKV);
    cudaGetSymbolAddress((void**)&ATT, g_ATT);
    cudaGetSymbolAddress((void**)&FF,  g_FF);

    cudaFuncSetAttribute((const void*)attn_kernel,
                         cudaFuncAttributeMaxDynamicSharedMemorySize, ASMEM);

    const float* xin = x;   // layer 0 reads input directly; residual writes into g_X
    for (int l = 0; l < DEPTH; l++) {
        ln_kernel<<<ROWS, 128>>>(xin, ln1g + l * DIMD, ln1b + l * DIMD, H);
        gemm_kernel<0><<<dim3(3 * INNERD / GBN, ROWS / GBM), 256>>>(
            H, Wqkv + (size_t)l * DIMD * 3 * INNERD, nullptr, nullptr,
            QKV, ROWS, 3 * INNERD, DIMD);
        attn_kernel<<<dim3(SEQ / AT, NHEAD, BATCH), 256, ASMEM>>>(QKV, ATT);
        gemm_kernel<0><<<dim3(DIMD / GBN, ROWS / GBM), 256>>>(
            ATT, Wo + (size_t)l * INNERD * DIMD, bo + l * DIMD, xin,
            X, ROWS, DIMD, INNERD);
        ln_kernel<<<ROWS, 128>>>(X, ln2g + l * DIMD, ln2b + l * DIMD, H);
        gemm_kernel<1><<<dim3(MLPD / GBN, ROWS / GBM), 256>>>(
            H, W1 + (size_t)l * DIMD * MLPD, b1 + l * MLPD, nullptr,
            FF, ROWS, MLPD, DIMD);
        gemm_kernel<0><<<dim3(DIMD / GBN, ROWS / GBM), 256>>>(
            FF, W2 + (size_t)l * MLPD * DIMD, b2 + l * DIMD, X,
            X, ROWS, DIMD, MLPD);
        xin = X;
    }
    ln_kernel<<<ROWS, 128>>>(X, lnfg, lnfb, out);
}

// round 5
// speedup vs baseline: 1.4291x; 1.4291x over previous
#include <cuda_runtime.h>
#include <mma.h>
#include <math.h>

using namespace nvcuda;

#define DIMD   512
#define DEPTH  4
#define NHEAD  8
#define DHEAD  64
#define INNERD 512
#define MLPD   2048
#define SEQ    2048
#define BATCH  4
#define ROWS   (BATCH * SEQ)   // 8192
#define SCALEF 0.125f          // 64^-0.5

// ---------------- scratch (device globals: allocation-free) ----------------
__device__ float g_X[ROWS * DIMD];        // residual stream
__device__ float g_H[ROWS * DIMD];        // layernorm output
__device__ float g_QKV[ROWS * 3 * INNERD];
__device__ float g_ATT[ROWS * DIMD];
__device__ float g_FF[ROWS * MLPD];

// ---------------- LayerNorm: one block (128 threads) per row ----------------
__global__ void __launch_bounds__(128) ln_kernel(const float* __restrict__ in,
                                                 const float* __restrict__ g,
                                                 const float* __restrict__ b,
                                                 float* __restrict__ out) {
    int row = blockIdx.x;
    const float4* ip = (const float4*)(in + (size_t)row * DIMD);
    float4 v = ip[threadIdx.x];               // 128 threads * 4 = 512
    float s  = v.x + v.y + v.z + v.w;
    float s2 = v.x * v.x + v.y * v.y + v.z * v.z + v.w * v.w;
    __shared__ float red[8];
    #pragma unroll
    for (int o = 16; o; o >>= 1) {
        s  += __shfl_xor_sync(0xffffffffu, s,  o);
        s2 += __shfl_xor_sync(0xffffffffu, s2, o);
    }
    int wid = threadIdx.x >> 5, lane = threadIdx.x & 31;
    if (lane == 0) { red[wid] = s; red[4 + wid] = s2; }
    __syncthreads();
    s  = red[0] + red[1] + red[2] + red[3];
    s2 = red[4] + red[5] + red[6] + red[7];
    float mu  = s * (1.0f / DIMD);
    float var = s2 * (1.0f / DIMD) - mu * mu;
    float r = rsqrtf(var + 1e-5f);
    int c = threadIdx.x * 4;
    float4 gv = *(const float4*)(g + c);
    float4 bv = *(const float4*)(b + c);
    float4 o;
    o.x = (v.x - mu) * r * gv.x + bv.x;
    o.y = (v.y - mu) * r * gv.y + bv.y;
    o.z = (v.z - mu) * r * gv.z + bv.z;
    o.w = (v.w - mu) * r * gv.w + bv.w;
    ((float4*)(out + (size_t)row * DIMD))[threadIdx.x] = o;
}

// ---------------- tf32 GEMM: C = act(A@B + bias) + resid -------------------
// Block tile 128x64, BK=16, 8 warps of 32x32 (2x2 m16n16k8 frags).
// A-stage padded to stride 20 (80B, 16B-aligned): kills the 8-way bank
// conflict of stride-16 A-fragment loads (row*16 mod 32 hits 2 offsets only;
// row*20 mod 32 hits 8 -> worst-case 2-way).
#define GBM 128
#define GBN 64
#define GBK 16
#define GLDA (GBK + 4)   // 20
#define GLDB (GBN + 8)   // 72
#define GLDC (GBN + 8)

__device__ __forceinline__ float gelu_exact(float x) {
    return 0.5f * x * (1.0f + erff(x * 0.70710678118654752f));
}

template <int ACT>
__global__ void __launch_bounds__(256) gemm_kernel(
    const float* __restrict__ A, const float* __restrict__ B,
    const float* __restrict__ bias, const float* __restrict__ resid,
    float* __restrict__ C, int M, int N, int K) {
    __shared__ __align__(16) union {
        struct { float As[GBM][GLDA]; float Bs[GBK][GLDB]; } ab[2];
        float Cs[GBM][GLDC];
    } sm;

    int tid = threadIdx.x;
    int wid = tid >> 5;
    int wm  = wid & 3;   // 0..3  (M)
    int wn  = wid >> 2;  // 0..1  (N)
    int bm = blockIdx.y * GBM;
    int bn = blockIdx.x * GBN;

    int ar0 = tid >> 2;            // A row for slot 0 (0..63)
    int ac  = (tid & 3) * 4;       // A col (0..12)
    int br  = tid >> 4;            // B row (0..15)
    int bc  = (tid & 15) * 4;      // B col (0..60)
    const float* Aptr = A + (size_t)(bm + ar0) * K + ac;
    const float* Bptr = B + (size_t)br * N + bn + bc;

    wmma::fragment<wmma::accumulator, 16, 16, 8, float> acc[2][2];
    #pragma unroll
    for (int im = 0; im < 2; im++)
        #pragma unroll
        for (int jn = 0; jn < 2; jn++) wmma::fill_fragment(acc[im][jn], 0.0f);

    float4 ra0 = *(const float4*)(Aptr);
    float4 ra1 = *(const float4*)(Aptr + (size_t)64 * K);
    float4 rb  = *(const float4*)(Bptr);

    int buf = 0;
    for (int k0 = 0; k0 < K; k0 += GBK) {
        {
            float* as0 = &sm.ab[buf].As[ar0][ac];
            as0[0] = wmma::__float_to_tf32(ra0.x);
            as0[1] = wmma::__float_to_tf32(ra0.y);
            as0[2] = wmma::__float_to_tf32(ra0.z);
            as0[3] = wmma::__float_to_tf32(ra0.w);
            float* as1 = &sm.ab[buf].As[64 + ar0][ac];
            as1[0] = wmma::__float_to_tf32(ra1.x);
            as1[1] = wmma::__float_to_tf32(ra1.y);
            as1[2] = wmma::__float_to_tf32(ra1.z);
            as1[3] = wmma::__float_to_tf32(ra1.w);
            float* bs = &sm.ab[buf].Bs[br][bc];
            bs[0] = wmma::__float_to_tf32(rb.x);
            bs[1] = wmma::__float_to_tf32(rb.y);
            bs[2] = wmma::__float_to_tf32(rb.z);
            bs[3] = wmma::__float_to_tf32(rb.w);
        }
        __syncthreads();

        if (k0 + GBK < K) {
            const float* ap = Aptr + (k0 + GBK);
            ra0 = *(const float4*)(ap);
            ra1 = *(const float4*)(ap + (size_t)64 * K);
            rb  = *(const float4*)(Bptr + (size_t)(k0 + GBK) * N);
        }

        #pragma unroll
        for (int kk = 0; kk < 2; kk++) {
            wmma::fragment<wmma::matrix_a, 16, 16, 8, wmma::precision::tf32, wmma::row_major> af[2];
            wmma::fragment<wmma::matrix_b, 16, 16, 8, wmma::precision::tf32, wmma::row_major> bf[2];
            #pragma unroll
            for (int im = 0; im < 2; im++)
                wmma::load_matrix_sync(af[im], &sm.ab[buf].As[wm * 32 + im * 16][kk * 8], GLDA);
            #pragma unroll
            for (int jn = 0; jn < 2; jn++)
                wmma::load_matrix_sync(bf[jn], &sm.ab[buf].Bs[kk * 8][wn * 32 + jn * 16], GLDB);
            #pragma unroll
            for (int im = 0; im < 2; im++)
                #pragma unroll
                for (int jn = 0; jn < 2; jn++)
                    wmma::mma_sync(acc[im][jn], af[im], bf[jn], acc[im][jn]);
        }
        buf ^= 1;
    }
    __syncthreads();

    #pragma unroll
    for (int im = 0; im < 2; im++)
        #pragma unroll
        for (int jn = 0; jn < 2; jn++)
            wmma::store_matrix_sync(&sm.Cs[wm * 32 + im * 16][wn * 32 + jn * 16],
                                    acc[im][jn], GLDC, wmma::mem_row_major);
    __syncthreads();

    #pragma unroll
    for (int i = 0; i < 8; i++) {
        int f = tid + i * 256;   // 0..2047
        int r = f >> 4;
        int c = (f & 15) * 4;
        float4 v = *(float4*)&sm.Cs[r][c];
        if (bias) {
            float4 bv = *(const float4*)(bias + bn + c);
            v.x += bv.x; v.y += bv.y; v.z += bv.z; v.w += bv.w;
        }
        if (ACT == 1) {
            v.x = gelu_exact(v.x); v.y = gelu_exact(v.y);
            v.z = gelu_exact(v.z); v.w = gelu_exact(v.w);
        }
        size_t off = (size_t)(bm + r) * N + bn + c;
        if (resid) {
            float4 rv = *(const float4*)(resid + off);
            v.x += rv.x; v.y += rv.y; v.z += rv.z; v.w += rv.w;
        }
        *(float4*)(C + off) = v;
    }
}

// ---------------- flash attention v2: register-resident accumulators -------
// Block = 128 queries x 1 head. 8 warps, each owns 16 query rows.
// Q/O/S/m/l all in registers (mma.m16n8k8 tf32 with documented layouts).
// K/V double-buffered in smem (1 __syncthreads per KV tile), P converted
// acc->A layout via per-warp smem scratch (warp-local, __syncwarp only).
#define BQ   128
#define BKV  64
#define LDK  72
#define LDP  72
#define STAGE_F (2 * BKV * LDK)          // floats per stage (K + V)
#define ASMEM  ((2 * STAGE_F + 8 * 16 * LDP) * (int)sizeof(float))  // 110592 B

__device__ __forceinline__ void mma_tf32(float c[4], const unsigned a[4],
                                         unsigned b0, unsigned b1) {
    asm volatile(
        "mma.sync.aligned.m16n8k8.row.col.f32.tf32.tf32.f32 "
        "{%0,%1,%2,%3}, {%4,%5,%6,%7}, {%8,%9}, {%0,%1,%2,%3};"
        : "+f"(c[0]), "+f"(c[1]), "+f"(c[2]), "+f"(c[3])
        : "r"(a[0]), "r"(a[1]), "r"(a[2]), "r"(a[3]), "r"(b0), "r"(b1));
}

__global__ void __launch_bounds__(256) attn_kernel(const float* __restrict__ qkv,
                                                   float* __restrict__ outp) {
    extern __shared__ __align__(16) float sh[];
    float* scratch = sh + 2 * STAGE_F;       // per-warp P scratch

    int tid  = threadIdx.x;
    int wid  = tid >> 5;
    int lane = tid & 31;
    int gq   = lane >> 2;     // group id 0..7  (row within fragment)
    int tg   = lane & 3;      // thread-in-group (col)
    int b = blockIdx.z, h = blockIdx.y;
    int q0 = blockIdx.x * BQ;
    size_t baserow = (size_t)b * SEQ;
    const float* qkvh = qkv + h * DHEAD;

    // ---- stage Q (scaled, tf32) into sh[0 .. 128*LDK) (aliases stage 0) ----
    #pragma unroll
    for (int i = 0; i < 8; i++) {
        int f = tid + i * 256;             // 0..2047
        int r = f >> 4;                    // 0..127
        int c = (f & 15) * 4;              // 0..60
        float4 v = *(const float4*)(qkvh + (baserow + q0 + r) * (3 * INNERD) + c);
        float* dst = &sh[r * LDK + c];
        dst[0] = wmma::__float_to_tf32(v.x * SCALEF);
        dst[1] = wmma::__float_to_tf32(v.y * SCALEF);
        dst[2] = wmma::__float_to_tf32(v.z * SCALEF);
        dst[3] = wmma::__float_to_tf32(v.w * SCALEF);
    }
    __syncthreads();

    // ---- read Q A-fragments (persistent) ----
    unsigned qf[8][4];
    {
        const float* Qw = sh + (wid * 16) * LDK;
        #pragma unroll
        for (int kc = 0; kc < 8; kc++) {
            qf[kc][0] = __float_as_uint(Qw[(gq)     * LDK + kc * 8 + tg]);
            qf[kc][1] = __float_as_uint(Qw[(gq + 8) * LDK + kc * 8 + tg]);
            qf[kc][2] = __float_as_uint(Qw[(gq)     * LDK + kc * 8 + tg + 4]);
            qf[kc][3] = __float_as_uint(Qw[(gq + 8) * LDK + kc * 8 + tg + 4]);
        }
    }

    // ---- prefetch KV tile 0 ----
    float4 pk[4], pv[4];
    #pragma unroll
    for (int i = 0; i < 4; i++) {
        int f = tid + i * 256;
        int r = f >> 4, c = (f & 15) * 4;
        const float* rowp = qkvh + (baserow + r) * (3 * INNERD) + c;
        pk[i] = *(const float4*)(rowp + INNERD);
        pv[i] = *(const float4*)(rowp + 2 * INNERD);
    }
    __syncthreads();   // all Q-frag reads complete before stage[0] overwrite

    float o[8][4];
    #pragma unroll
    for (int nc = 0; nc < 8; nc++) { o[nc][0] = o[nc][1] = o[nc][2] = o[nc][3] = 0.f; }
    float m_lo = -INFINITY, m_hi = -INFINITY, l_lo = 0.f, l_hi = 0.f;
    float* Pw = scratch + wid * 16 * LDP;

    int buf = 0;
    for (int j0 = 0; j0 < SEQ; j0 += BKV) {
        float* Ks = sh + buf * STAGE_F;
        float* Vs = Ks + BKV * LDK;
        #pragma unroll
        for (int i = 0; i < 4; i++) {
            int f = tid + i * 256;
            int r = f >> 4, c = (f & 15) * 4;
            float* kd = &Ks[r * LDK + c];
            kd[0] = wmma::__float_to_tf32(pk[i].x);
            kd[1] = wmma::__float_to_tf32(pk[i].y);
            kd[2] = wmma::__float_to_tf32(pk[i].z);
            kd[3] = wmma::__float_to_tf32(pk[i].w);
            float* vd = &Vs[r * LDK + c];
            vd[0] = wmma::__float_to_tf32(pv[i].x);
            vd[1] = wmma::__float_to_tf32(pv[i].y);
            vd[2] = wmma::__float_to_tf32(pv[i].z);
            vd[3] = wmma::__float_to_tf32(pv[i].w);
        }
        __syncthreads();

        // prefetch next tile (latency hides behind S/softmax/PV)
        if (j0 + BKV < SEQ) {
            #pragma unroll
            for (int i = 0; i < 4; i++) {
                int f = tid + i * 256;
                int r = f >> 4, c = (f & 15) * 4;
                const float* rowp = qkvh + (baserow + j0 + BKV + r) * (3 * INNERD) + c;
                pk[i] = *(const float4*)(rowp + INNERD);
                pv[i] = *(const float4*)(rowp + 2 * INNERD);
            }
        }

        // ---- S = Q @ K^T (16x64 per warp, in registers) ----
        float s[8][4];
        #pragma unroll
        for (int nc = 0; nc < 8; nc++) { s[nc][0] = s[nc][1] = s[nc][2] = s[nc][3] = 0.f; }
        #pragma unroll
        for (int kc = 0; kc < 8; kc++) {
            #pragma unroll
            for (int nc = 0; nc < 8; nc++) {
                unsigned b0 = __float_as_uint(Ks[(nc * 8 + gq) * LDK + kc * 8 + tg]);
                unsigned b1 = __float_as_uint(Ks[(nc * 8 + gq) * LDK + kc * 8 + tg + 4]);
                mma_tf32(s[nc], qf[kc], b0, b1);
            }
        }

        // ---- online softmax, all in registers (quad shuffles) ----
        float tmax_lo = -INFINITY, tmax_hi = -INFINITY;
        #pragma unroll
        for (int nc = 0; nc < 8; nc++) {
            tmax_lo = fmaxf(tmax_lo, fmaxf(s[nc][0], s[nc][1]));
            tmax_hi = fmaxf(tmax_hi, fmaxf(s[nc][2], s[nc][3]));
        }
        tmax_lo = fmaxf(tmax_lo, __shfl_xor_sync(0xffffffffu, tmax_lo, 1));
        tmax_lo = fmaxf(tmax_lo, __shfl_xor_sync(0xffffffffu, tmax_lo, 2));
        tmax_hi = fmaxf(tmax_hi, __shfl_xor_sync(0xffffffffu, tmax_hi, 1));
        tmax_hi = fmaxf(tmax_hi, __shfl_xor_sync(0xffffffffu, tmax_hi, 2));
        float mn_lo = fmaxf(m_lo, tmax_lo);
        float mn_hi = fmaxf(m_hi, tmax_hi);
        float al_lo = __expf(m_lo - mn_lo);
        float al_hi = __expf(m_hi - mn_hi);
        float sum_lo = 0.f, sum_hi = 0.f;
        #pragma unroll
        for (int nc = 0; nc < 8; nc++) {
            s[nc][0] = __expf(s[nc][0] - mn_lo);
            s[nc][1] = __expf(s[nc][1] - mn_lo);
            s[nc][2] = __expf(s[nc][2] - mn_hi);
            s[nc][3] = __expf(s[nc][3] - mn_hi);
            sum_lo += s[nc][0] + s[nc][1];
            sum_hi += s[nc][2] + s[nc][3];
        }
        sum_lo += __shfl_xor_sync(0xffffffffu, sum_lo, 1);
        sum_lo += __shfl_xor_sync(0xffffffffu, sum_lo, 2);
        sum_hi += __shfl_xor_sync(0xffffffffu, sum_hi, 1);
        sum_hi += __shfl_xor_sync(0xffffffffu, sum_hi, 2);
        l_lo = l_lo * al_lo + sum_lo;
        l_hi = l_hi * al_hi + sum_hi;
        m_lo = mn_lo; m_hi = mn_hi;
        #pragma unroll
        for (int nc = 0; nc < 8; nc++) {
            o[nc][0] *= al_lo; o[nc][1] *= al_lo;
            o[nc][2] *= al_hi; o[nc][3] *= al_hi;
        }

        // ---- P: acc layout -> A layout via per-warp scratch ----
        __syncwarp();
        #pragma unroll
        for (int nc = 0; nc < 8; nc++) {
            float2 w0 = make_float2(wmma::__float_to_tf32(s[nc][0]),
                                    wmma::__float_to_tf32(s[nc][1]));
            float2 w1 = make_float2(wmma::__float_to_tf32(s[nc][2]),
                                    wmma::__float_to_tf32(s[nc][3]));
            *(float2*)&Pw[(gq)     * LDP + nc * 8 + 2 * tg] = w0;
            *(float2*)&Pw[(gq + 8) * LDP + nc * 8 + 2 * tg] = w1;
        }
        __syncwarp();

        // ---- O += P @ V ----
        #pragma unroll
        for (int kc = 0; kc < 8; kc++) {
            unsigned a[4];
            a[0] = __float_as_uint(Pw[(gq)     * LDP + kc * 8 + tg]);
            a[1] = __float_as_uint(Pw[(gq + 8) * LDP + kc * 8 + tg]);
            a[2] = __float_as_uint(Pw[(gq)     * LDP + kc * 8 + tg + 4]);
            a[3] = __float_as_uint(Pw[(gq + 8) * LDP + kc * 8 + tg + 4]);
            #pragma unroll
            for (int nc = 0; nc < 8; nc++) {
                unsigned b0 = __float_as_uint(Vs[(kc * 8 + tg)     * LDK + nc * 8 + gq]);
                unsigned b1 = __float_as_uint(Vs[(kc * 8 + tg + 4) * LDK + nc * 8 + gq]);
                mma_tf32(o[nc], a, b0, b1);
            }
        }
        buf ^= 1;
    }

    // ---- epilogue: O /= l, write [b, n, h*64 + d] ----
    float inv_lo = 1.0f / l_lo;
    float inv_hi = 1.0f / l_hi;
    {
        float* dst_lo = outp + (baserow + q0 + wid * 16 + gq)     * DIMD + h * DHEAD + 2 * tg;
        float* dst_hi = outp + (baserow + q0 + wid * 16 + gq + 8) * DIMD + h * DHEAD + 2 * tg;
        #pragma unroll
        for (int nc = 0; nc < 8; nc++) {
            *(float2*)&dst_lo[nc * 8] = make_float2(o[nc][0] * inv_lo, o[nc][1] * inv_lo);
            *(float2*)&dst_hi[nc * 8] = make_float2(o[nc][2] * inv_hi, o[nc][3] * inv_hi);
        }
    }
}

// ---------------- launch ----------------
extern "C" void kernel_launch(void* const* d_in, const int* in_sizes, int n_in,
                              void* d_out, int out_size) {
    (void)in_sizes; (void)n_in; (void)out_size;
    const float* x    = (const float*)d_in[0];
    const float* Wqkv = (const float*)d_in[1];
    const float* Wo   = (const float*)d_in[2];
    const float* bo   = (const float*)d_in[3];
    const float* ln1g = (const float*)d_in[4];
    const float* ln1b = (const float*)d_in[5];
    const float* W1   = (const float*)d_in[6];
    const float* b1   = (const float*)d_in[7];
    const float* W2   = (const float*)d_in[8];
    const float* b2   = (const float*)d_in[9];
    const float* ln2g = (const float*)d_in[10];
    const float* ln2b = (const float*)d_in[11];
    const float* lnfg = (const float*)d_in[12];
    const float* lnfb = (const float*)d_in[13];
    float* out = (float*)d_out;

    float *X, *H, *QKV, *ATT, *FF;
    cudaGetSymbolAddress((void**)&X,   g_X);
    cudaGetSymbolAddress((void**)&H,   g_H);
    cudaGetSymbolAddress((void**)&QKV, g_QKV);
    cudaGetSymbolAddress((void**)&ATT, g_ATT);
    cudaGetSymbolAddress((void**)&FF,  g_FF);

    cudaFuncSetAttribute((const void*)attn_kernel,
                         cudaFuncAttributeMaxDynamicSharedMemorySize, ASMEM);

    const float* xin = x;   // layer 0 reads input directly; residual writes into g_X
    for (int l = 0; l < DEPTH; l++) {
        ln_kernel<<<ROWS, 128>>>(xin, ln1g + l * DIMD, ln1b + l * DIMD, H);
        gemm_kernel<0><<<dim3(3 * INNERD / GBN, ROWS / GBM), 256>>>(
            H, Wqkv + (size_t)l * DIMD * 3 * INNERD, nullptr, nullptr,
            QKV, ROWS, 3 * INNERD, DIMD);
        attn_kernel<<<dim3(SEQ / BQ, NHEAD, BATCH), 256, ASMEM>>>(QKV, ATT);
        gemm_kernel<0><<<dim3(DIMD / GBN, ROWS / GBM), 256>>>(
            ATT, Wo + (size_t)l * INNERD * DIMD, bo + l * DIMD, xin,
            X, ROWS, DIMD, INNERD);
        ln_kernel<<<ROWS, 128>>>(X, ln2g + l * DIMD, ln2b + l * DIMD, H);
        gemm_kernel<1><<<dim3(MLPD / GBN, ROWS / GBM), 256>>>(
            H, W1 + (size_t)l * DIMD * MLPD, b1 + l * MLPD, nullptr,
            FF, ROWS, MLPD, DIMD);
        gemm_kernel<0><<<dim3(DIMD / GBN, ROWS / GBM), 256>>>(
            FF, W2 + (size_t)l * MLPD * DIMD, b2 + l * DIMD, X,
            X, ROWS, DIMD, MLPD);
        xin = X;
    }
    ln_kernel<<<ROWS, 128>>>(X, lnfg, lnfb, out);
}

// round 11
// speedup vs baseline: 1.6065x; 1.1241x over previous
#include <cuda_runtime.h>
#include <mma.h>
#include <math.h>

using namespace nvcuda;

#define DIMD   512
#define DEPTH  4
#define NHEAD  8
#define DHEAD  64
#define INNERD 512
#define MLPD   2048
#define SEQ    2048
#define BATCH  4
#define ROWS   (BATCH * SEQ)   // 8192
#define SCALEF 0.125f          // 64^-0.5

// ---------------- scratch (device globals: allocation-free) ----------------
__device__ float g_X[ROWS * DIMD];        // residual stream
__device__ float g_H[ROWS * DIMD];        // layernorm output
__device__ float g_QKV[ROWS * 3 * INNERD];
__device__ float g_ATT[ROWS * DIMD];
__device__ float g_FF[ROWS * MLPD];

// ---------------- LayerNorm: one block (128 threads) per row ----------------
__global__ void __launch_bounds__(128) ln_kernel(const float* __restrict__ in,
                                                 const float* __restrict__ g,
                                                 const float* __restrict__ b,
                                                 float* __restrict__ out) {
    int row = blockIdx.x;
    const float4* ip = (const float4*)(in + (size_t)row * DIMD);
    float4 v = ip[threadIdx.x];               // 128 threads * 4 = 512
    float s  = v.x + v.y + v.z + v.w;
    float s2 = v.x * v.x + v.y * v.y + v.z * v.z + v.w * v.w;
    __shared__ float red[8];
    #pragma unroll
    for (int o = 16; o; o >>= 1) {
        s  += __shfl_xor_sync(0xffffffffu, s,  o);
        s2 += __shfl_xor_sync(0xffffffffu, s2, o);
    }
    int wid = threadIdx.x >> 5, lane = threadIdx.x & 31;
    if (lane == 0) { red[wid] = s; red[4 + wid] = s2; }
    __syncthreads();
    s  = red[0] + red[1] + red[2] + red[3];
    s2 = red[4] + red[5] + red[6] + red[7];
    float mu  = s * (1.0f / DIMD);
    float var = s2 * (1.0f / DIMD) - mu * mu;
    float r = rsqrtf(var + 1e-5f);
    int c = threadIdx.x * 4;
    float4 gv = *(const float4*)(g + c);
    float4 bv = *(const float4*)(b + c);
    float4 o;
    o.x = (v.x - mu) * r * gv.x + bv.x;
    o.y = (v.y - mu) * r * gv.y + bv.y;
    o.z = (v.z - mu) * r * gv.z + bv.z;
    o.w = (v.w - mu) * r * gv.w + bv.w;
    ((float4*)(out + (size_t)row * DIMD))[threadIdx.x] = o;
}

// ---------------- tf32 GEMM: C = act(A@B + bias) + resid -------------------
// Block tile 128x128, BK=16, 8 warps of 32x64 (2x4 m16n16k8 frags).
// Register-prefetch + double-buffered smem, one barrier per K-chunk.
// Epilogue in two 64-col passes through the shared Cs buffer.
#define GBM 128
#define GBN 128
#define GBK 16
#define GLDA (GBK + 4)    // 20
#define GLDB (GBN + 8)    // 136 (== 72 mod 32: same bank behavior as before)
#define GLDC (64 + 8)     // 72, half-width epilogue buffer

__device__ __forceinline__ float gelu_exact(float x) {
    return 0.5f * x * (1.0f + erff(x * 0.70710678118654752f));
}

template <int ACT>
__global__ void __launch_bounds__(256, 2) gemm_kernel(
    const float* __restrict__ A, const float* __restrict__ B,
    const float* __restrict__ bias, const float* __restrict__ resid,
    float* __restrict__ C, int M, int N, int K) {
    __shared__ __align__(16) union {
        struct { float As[GBM][GLDA]; float Bs[GBK][GLDB]; } ab[2];
        float Cs[GBM][GLDC];
    } sm;

    int tid = threadIdx.x;
    int wid = tid >> 5;
    int wm  = wid & 3;   // 0..3  (M: 32-row slab)
    int wn  = wid >> 2;  // 0..1  (N: 64-col slab)
    int bm = blockIdx.y * GBM;
    int bn = blockIdx.x * GBN;

    int ar0 = tid >> 2;            // A row for slot 0 (0..63)
    int ac  = (tid & 3) * 4;       // A col (0..12)
    int br  = tid >> 5;            // B row (0..7), second slot +8
    int bc  = (tid & 31) * 4;      // B col (0..124)
    const float* Aptr = A + (size_t)(bm + ar0) * K + ac;
    const float* Bptr = B + (size_t)br * N + bn + bc;

    wmma::fragment<wmma::accumulator, 16, 16, 8, float> acc[2][4];
    #pragma unroll
    for (int im = 0; im < 2; im++)
        #pragma unroll
        for (int jn = 0; jn < 4; jn++) wmma::fill_fragment(acc[im][jn], 0.0f);

    // prefetch first K-chunk into registers
    float4 ra0 = *(const float4*)(Aptr);
    float4 ra1 = *(const float4*)(Aptr + (size_t)64 * K);
    float4 rb0 = *(const float4*)(Bptr);
    float4 rb1 = *(const float4*)(Bptr + (size_t)8 * N);

    int buf = 0;
    for (int k0 = 0; k0 < K; k0 += GBK) {
        // store current chunk (tf32-rounded) into stage `buf`
        {
            float* as0 = &sm.ab[buf].As[ar0][ac];
            as0[0] = wmma::__float_to_tf32(ra0.x);
            as0[1] = wmma::__float_to_tf32(ra0.y);
            as0[2] = wmma::__float_to_tf32(ra0.z);
            as0[3] = wmma::__float_to_tf32(ra0.w);
            float* as1 = &sm.ab[buf].As[64 + ar0][ac];
            as1[0] = wmma::__float_to_tf32(ra1.x);
            as1[1] = wmma::__float_to_tf32(ra1.y);
            as1[2] = wmma::__float_to_tf32(ra1.z);
            as1[3] = wmma::__float_to_tf32(ra1.w);
            float* bs0 = &sm.ab[buf].Bs[br][bc];
            bs0[0] = wmma::__float_to_tf32(rb0.x);
            bs0[1] = wmma::__float_to_tf32(rb0.y);
            bs0[2] = wmma::__float_to_tf32(rb0.z);
            bs0[3] = wmma::__float_to_tf32(rb0.w);
            float* bs1 = &sm.ab[buf].Bs[br + 8][bc];
            bs1[0] = wmma::__float_to_tf32(rb1.x);
            bs1[1] = wmma::__float_to_tf32(rb1.y);
            bs1[2] = wmma::__float_to_tf32(rb1.z);
            bs1[3] = wmma::__float_to_tf32(rb1.w);
        }
        __syncthreads();

        // issue next chunk's loads early (latency hides behind the MMAs)
        if (k0 + GBK < K) {
            const float* ap = Aptr + (k0 + GBK);
            ra0 = *(const float4*)(ap);
            ra1 = *(const float4*)(ap + (size_t)64 * K);
            const float* bp = Bptr + (size_t)(k0 + GBK) * N;
            rb0 = *(const float4*)(bp);
            rb1 = *(const float4*)(bp + (size_t)8 * N);
        }

        #pragma unroll
        for (int kk = 0; kk < 2; kk++) {
            wmma::fragment<wmma::matrix_a, 16, 16, 8, wmma::precision::tf32, wmma::row_major> af[2];
            wmma::fragment<wmma::matrix_b, 16, 16, 8, wmma::precision::tf32, wmma::row_major> bf[4];
            #pragma unroll
            for (int im = 0; im < 2; im++)
                wmma::load_matrix_sync(af[im], &sm.ab[buf].As[wm * 32 + im * 16][kk * 8], GLDA);
            #pragma unroll
            for (int jn = 0; jn < 4; jn++)
                wmma::load_matrix_sync(bf[jn], &sm.ab[buf].Bs[kk * 8][wn * 64 + jn * 16], GLDB);
            #pragma unroll
            for (int im = 0; im < 2; im++)
                #pragma unroll
                for (int jn = 0; jn < 4; jn++)
                    wmma::mma_sync(acc[im][jn], af[im], bf[jn], acc[im][jn]);
        }
        buf ^= 1;
        // single barrier per chunk: next iteration's barrier orders reads of
        // this stage before the iteration-after-next overwrites it.
    }
    __syncthreads();   // all MMAs done before Cs aliases stage memory

    // ---- epilogue: two 64-col passes through Cs ----
    #pragma unroll
    for (int p = 0; p < 2; p++) {
        if (wn == p) {
            #pragma unroll
            for (int im = 0; im < 2; im++)
                #pragma unroll
                for (int jn = 0; jn < 4; jn++)
                    wmma::store_matrix_sync(&sm.Cs[wm * 32 + im * 16][jn * 16],
                                            acc[im][jn], GLDC, wmma::mem_row_major);
        }
        __syncthreads();
        #pragma unroll
        for (int i = 0; i < 8; i++) {
            int f = tid + i * 256;   // 0..2047
            int r = f >> 4;          // 0..127
            int c = (f & 15) * 4;    // 0..60
            float4 v = *(float4*)&sm.Cs[r][c];
            int col = bn + p * 64 + c;
            if (bias) {
                float4 bv = *(const float4*)(bias + col);
                v.x += bv.x; v.y += bv.y; v.z += bv.z; v.w += bv.w;
            }
            if (ACT == 1) {
                v.x = gelu_exact(v.x); v.y = gelu_exact(v.y);
                v.z = gelu_exact(v.z); v.w = gelu_exact(v.w);
            }
            size_t off = (size_t)(bm + r) * N + col;
            if (resid) {
                float4 rv = *(const float4*)(resid + off);
                v.x += rv.x; v.y += rv.y; v.z += rv.z; v.w += rv.w;
            }
            *(float4*)(C + off) = v;
        }
        __syncthreads();   // pass-0 reads done before pass-1 overwrites Cs
    }
}

// ---------------- flash attention v3 ----------------------------------------
#define BQ   128
#define BKV  64
#define LDK  72
#define STAGE_F (2 * BKV * LDK)                      // 9216 floats per stage
#define ASMEM  (2 * STAGE_F * (int)sizeof(float))    // 73728 B

#define CP_ASYNC16(dst_u32, src_ptr) \
    asm volatile("cp.async.cg.shared.global [%0], [%1], 16;" \
                 :: "r"(dst_u32), "l"(src_ptr))
#define CP_COMMIT() asm volatile("cp.async.commit_group;")
#define CP_WAIT1()  asm volatile("cp.async.wait_group 1;")
#define CP_WAIT0()  asm volatile("cp.async.wait_group 0;")

__device__ __forceinline__ void mma_tf32(float c[4], const unsigned a[4],
                                         unsigned b0, unsigned b1) {
    asm volatile(
        "mma.sync.aligned.m16n8k8.row.col.f32.tf32.tf32.f32 "
        "{%0,%1,%2,%3}, {%4,%5,%6,%7}, {%8,%9}, {%0,%1,%2,%3};"
        : "+f"(c[0]), "+f"(c[1]), "+f"(c[2]), "+f"(c[3])
        : "r"(a[0]), "r"(a[1]), "r"(a[2]), "r"(a[3]), "r"(b0), "r"(b1));
}

__global__ void __launch_bounds__(256, 2) attn_kernel(const float* __restrict__ qkv,
                                                      float* __restrict__ outp) {
    extern __shared__ __align__(16) float sh[];

    int tid  = threadIdx.x;
    int wid  = tid >> 5;
    int lane = tid & 31;
    int gq   = lane >> 2;     // 0..7 row within fragment
    int tg   = lane & 3;      // 0..3 col group
    int qbase = lane & 28;    // lane of (gq, tg=0)
    int b = blockIdx.z, h = blockIdx.y;
    int q0 = blockIdx.x * BQ;
    size_t baserow = (size_t)b * SEQ;
    const float* qkvh = qkv + h * DHEAD;

    // staging coords (4 quads per thread)
    int sr[4], sc[4];
    #pragma unroll
    for (int i = 0; i < 4; i++) {
        int f = tid + i * 256;
        sr[i] = f >> 4;               // 0..63
        sc[i] = (f & 15) * 4;         // 0..60
    }

    // ---- stage Q (scaled, tf32-rounded) into stage0 region temporarily ----
    #pragma unroll
    for (int i = 0; i < 8; i++) {
        int f = tid + i * 256;
        int r = f >> 4;                // 0..127
        int c = (f & 15) * 4;
        float4 v = *(const float4*)(qkvh + (baserow + q0 + r) * (3 * INNERD) + c);
        float* dst = &sh[r * LDK + c];
        dst[0] = wmma::__float_to_tf32(v.x * SCALEF);
        dst[1] = wmma::__float_to_tf32(v.y * SCALEF);
        dst[2] = wmma::__float_to_tf32(v.z * SCALEF);
        dst[3] = wmma::__float_to_tf32(v.w * SCALEF);
    }
    __syncthreads();

    // ---- read persistent Q A-fragments ----
    unsigned qf[8][4];
    {
        const float* Qw = sh + (wid * 16) * LDK;
        #pragma unroll
        for (int kc = 0; kc < 8; kc++) {
            qf[kc][0] = __float_as_uint(Qw[(gq)     * LDK + kc * 8 + tg]);
            qf[kc][1] = __float_as_uint(Qw[(gq + 8) * LDK + kc * 8 + tg]);
            qf[kc][2] = __float_as_uint(Qw[(gq)     * LDK + kc * 8 + tg + 4]);
            qf[kc][3] = __float_as_uint(Qw[(gq + 8) * LDK + kc * 8 + tg + 4]);
        }
    }
    __syncthreads();   // Q-frag reads complete before cp.async overwrites stage0

    // ---- cp.async staging helper (8 x 16B per thread per stage) ----
    auto stage_kv = [&](int jbase, int bufsel) {
        float* Ks = sh + bufsel * STAGE_F;
        float* Vs = Ks + BKV * LDK;
        #pragma unroll
        for (int i = 0; i < 4; i++) {
            int r = sr[i], c = sc[i];
            const float* rowp = qkvh + (baserow + jbase + r) * (3 * INNERD) + c;
            unsigned kd = (unsigned)__cvta_generic_to_shared(&Ks[r * LDK + c]);
            unsigned vd = (unsigned)__cvta_generic_to_shared(&Vs[r * LDK + c]);
            CP_ASYNC16(kd, rowp + INNERD);
            CP_ASYNC16(vd, rowp + 2 * INNERD);
        }
    };

    stage_kv(0, 0);
    CP_COMMIT();

    float o[8][4];
    #pragma unroll
    for (int nc = 0; nc < 8; nc++) { o[nc][0] = o[nc][1] = o[nc][2] = o[nc][3] = 0.f; }
    float m_lo = -INFINITY, m_hi = -INFINITY, l_lo = 0.f, l_hi = 0.f;

    for (int j0 = 0, it = 0; j0 < SEQ; j0 += BKV, it++) {
        int buf = it & 1;
        if (j0 + BKV < SEQ) {
            stage_kv(j0 + BKV, buf ^ 1);   // prev readers of buf^1 done (trailing bar)
            CP_COMMIT();
            CP_WAIT1();                    // current stage retired
        } else {
            CP_WAIT0();
        }
        __syncthreads();

        const float* Ks = sh + buf * STAGE_F;
        const float* Vs = Ks + BKV * LDK;

        // ---- S = Q @ K^T (raw f32 bits as tf32; truncation) ----
        float s[8][4];
        #pragma unroll
        for (int nc = 0; nc < 8; nc++) { s[nc][0] = s[nc][1] = s[nc][2] = s[nc][3] = 0.f; }
        #pragma unroll
        for (int kc = 0; kc < 8; kc++) {
            #pragma unroll
            for (int nc = 0; nc < 8; nc++) {
                unsigned b0 = __float_as_uint(Ks[(nc * 8 + gq) * LDK + kc * 8 + tg]);
                unsigned b1 = __float_as_uint(Ks[(nc * 8 + gq) * LDK + kc * 8 + tg + 4]);
                mma_tf32(s[nc], qf[kc], b0, b1);
            }
        }

        // ---- online softmax (registers + quad shuffles) ----
        float tmax_lo = -INFINITY, tmax_hi = -INFINITY;
        #pragma unroll
        for (int nc = 0; nc < 8; nc++) {
            tmax_lo = fmaxf(tmax_lo, fmaxf(s[nc][0], s[nc][1]));
            tmax_hi = fmaxf(tmax_hi, fmaxf(s[nc][2], s[nc][3]));
        }
        tmax_lo = fmaxf(tmax_lo, __shfl_xor_sync(0xffffffffu, tmax_lo, 1));
        tmax_lo = fmaxf(tmax_lo, __shfl_xor_sync(0xffffffffu, tmax_lo, 2));
        tmax_hi = fmaxf(tmax_hi, __shfl_xor_sync(0xffffffffu, tmax_hi, 1));
        tmax_hi = fmaxf(tmax_hi, __shfl_xor_sync(0xffffffffu, tmax_hi, 2));
        float mn_lo = fmaxf(m_lo, tmax_lo);
        float mn_hi = fmaxf(m_hi, tmax_hi);
        float al_lo = __expf(m_lo - mn_lo);
        float al_hi = __expf(m_hi - mn_hi);
        float sum_lo = 0.f, sum_hi = 0.f;
        #pragma unroll
        for (int nc = 0; nc < 8; nc++) {
            s[nc][0] = __expf(s[nc][0] - mn_lo);
            s[nc][1] = __expf(s[nc][1] - mn_lo);
            s[nc][2] = __expf(s[nc][2] - mn_hi);
            s[nc][3] = __expf(s[nc][3] - mn_hi);
            sum_lo += s[nc][0] + s[nc][1];
            sum_hi += s[nc][2] + s[nc][3];
        }
        sum_lo += __shfl_xor_sync(0xffffffffu, sum_lo, 1);
        sum_lo += __shfl_xor_sync(0xffffffffu, sum_lo, 2);
        sum_hi += __shfl_xor_sync(0xffffffffu, sum_hi, 1);
        sum_hi += __shfl_xor_sync(0xffffffffu, sum_hi, 2);
        l_lo = l_lo * al_lo + sum_lo;
        l_hi = l_hi * al_hi + sum_hi;
        m_lo = mn_lo; m_hi = mn_hi;
        #pragma unroll
        for (int nc = 0; nc < 8; nc++) {
            o[nc][0] *= al_lo; o[nc][1] *= al_lo;
            o[nc][2] *= al_hi; o[nc][3] *= al_hi;
        }

        // ---- O += P @ V : P acc->A layout via intra-quad shuffles ----
        #pragma unroll
        for (int kc = 0; kc < 8; kc++) {
            unsigned p0 = __float_as_uint(wmma::__float_to_tf32(s[kc][0]));
            unsigned p1 = __float_as_uint(wmma::__float_to_tf32(s[kc][1]));
            unsigned p2 = __float_as_uint(wmma::__float_to_tf32(s[kc][2]));
            unsigned p3 = __float_as_uint(wmma::__float_to_tf32(s[kc][3]));
            int s_lo = qbase + (tg >> 1);
            int s_hi = s_lo + 2;
            unsigned x0 = __shfl_sync(0xffffffffu, p0, s_lo);
            unsigned x1 = __shfl_sync(0xffffffffu, p1, s_lo);
            unsigned x2 = __shfl_sync(0xffffffffu, p2, s_lo);
            unsigned x3 = __shfl_sync(0xffffffffu, p3, s_lo);
            unsigned y0 = __shfl_sync(0xffffffffu, p0, s_hi);
            unsigned y1 = __shfl_sync(0xffffffffu, p1, s_hi);
            unsigned y2 = __shfl_sync(0xffffffffu, p2, s_hi);
            unsigned y3 = __shfl_sync(0xffffffffu, p3, s_hi);
            unsigned a[4];
            a[0] = (tg & 1) ? x1 : x0;
            a[1] = (tg & 1) ? x3 : x2;
            a[2] = (tg & 1) ? y1 : y0;
            a[3] = (tg & 1) ? y3 : y2;
            #pragma unroll
            for (int nc = 0; nc < 8; nc++) {
                unsigned b0 = __float_as_uint(Vs[(kc * 8 + tg)     * LDK + nc * 8 + gq]);
                unsigned b1 = __float_as_uint(Vs[(kc * 8 + tg + 4) * LDK + nc * 8 + gq]);
                mma_tf32(o[nc], a, b0, b1);
            }
        }
        __syncthreads();   // all reads of buf done before next issue overwrites it
    }

    // ---- epilogue: O /= l, write [b, n, h*64 + d] ----
    float inv_lo = 1.0f / l_lo;
    float inv_hi = 1.0f / l_hi;
    {
        float* dst_lo = outp + (baserow + q0 + wid * 16 + gq)     * DIMD + h * DHEAD + 2 * tg;
        float* dst_hi = outp + (baserow + q0 + wid * 16 + gq + 8) * DIMD + h * DHEAD + 2 * tg;
        #pragma unroll
        for (int nc = 0; nc < 8; nc++) {
            *(float2*)&dst_lo[nc * 8] = make_float2(o[nc][0] * inv_lo, o[nc][1] * inv_lo);
            *(float2*)&dst_hi[nc * 8] = make_float2(o[nc][2] * inv_hi, o[nc][3] * inv_hi);
        }
    }
}

// ---------------- launch ----------------
extern "C" void kernel_launch(void* const* d_in, const int* in_sizes, int n_in,
                              void* d_out, int out_size) {
    (void)in_sizes; (void)n_in; (void)out_size;
    const float* x    = (const float*)d_in[0];
    const float* Wqkv = (const float*)d_in[1];
    const float* Wo   = (const float*)d_in[2];
    const float* bo   = (const float*)d_in[3];
    const float* ln1g = (const float*)d_in[4];
    const float* ln1b = (const float*)d_in[5];
    const float* W1   = (const float*)d_in[6];
    const float* b1   = (const float*)d_in[7];
    const float* W2   = (const float*)d_in[8];
    const float* b2   = (const float*)d_in[9];
    const float* ln2g = (const float*)d_in[10];
    const float* ln2b = (const float*)d_in[11];
    const float* lnfg = (const float*)d_in[12];
    const float* lnfb = (const float*)d_in[13];
    float* out = (float*)d_out;

    float *X, *H, *QKV, *ATT, *FF;
    cudaGetSymbolAddress((void**)&X,   g_X);
    cudaGetSymbolAddress((void**)&H,   g_H);
    cudaGetSymbolAddress((void**)&QKV, g_QKV);
    cudaGetSymbolAddress((void**)&ATT, g_ATT);
    cudaGetSymbolAddress((void**)&FF,  g_FF);

    cudaFuncSetAttribute((const void*)attn_kernel,
                         cudaFuncAttributeMaxDynamicSharedMemorySize, ASMEM);

    const float* xin = x;   // layer 0 reads input directly; residual writes into g_X
    for (int l = 0; l < DEPTH; l++) {
        ln_kernel<<<ROWS, 128>>>(xin, ln1g + l * DIMD, ln1b + l * DIMD, H);
        gemm_kernel<0><<<dim3(3 * INNERD / GBN, ROWS / GBM), 256>>>(
            H, Wqkv + (size_t)l * DIMD * 3 * INNERD, nullptr, nullptr,
            QKV, ROWS, 3 * INNERD, DIMD);
        attn_kernel<<<dim3(SEQ / BQ, NHEAD, BATCH), 256, ASMEM>>>(QKV, ATT);
        gemm_kernel<0><<<dim3(DIMD / GBN, ROWS / GBM), 256>>>(
            ATT, Wo + (size_t)l * INNERD * DIMD, bo + l * DIMD, xin,
            X, ROWS, DIMD, INNERD);
        ln_kernel<<<ROWS, 128>>>(X, ln2g + l * DIMD, ln2b + l * DIMD, H);
        gemm_kernel<1><<<dim3(MLPD / GBN, ROWS / GBM), 256>>>(
            H, W1 + (size_t)l * DIMD * MLPD, b1 + l * MLPD, nullptr,
            FF, ROWS, MLPD, DIMD);
        gemm_kernel<0><<<dim3(DIMD / GBN, ROWS / GBM), 256>>>(
            FF, W2 + (size_t)l * MLPD * DIMD, b2 + l * DIMD, X,
            X, ROWS, DIMD, MLPD);
        xin = X;
    }
    ln_kernel<<<ROWS, 128>>>(X, lnfg, lnfb, out);
}